// round 6
// baseline (speedup 1.0000x reference)
#include <cuda_runtime.h>
#include <cuda_fp16.h>
#include <cstdint>

// Problem constants
#define DFEAT   128
#define KTOP    8
#define DEG     32
#define OUT_CH  128
#define XOUT    120
#define MAXN    10000

// GEMM: K = 2 parts * 81 = 162 valid, padded to 192 = 12 k-steps of 16
#define KVALID  162
#define KSTEPS  12
#define KU32    96         // u32 per row (192 fp16 / 2)
#define RST     104        // row stride u32 (96+8; mod 32 = 8 -> conflict-free LDS.64)
#define SELW2   136        // u32 row stride of staged sel rows
#define BUFU32  (128 * RST)

__device__ unsigned g_sel[MAXN * 9 * DFEAT];   // packed fp16: bhi | blo<<16

// ---------------------------------------------------------------------------
// fp16 mma.sync wrapper (m16n8k16, row.col, f32 accum)
// ---------------------------------------------------------------------------
__device__ __forceinline__ void mma_fp16(
    float& c0, float& c1, float& c2, float& c3,
    uint32_t a0, uint32_t a1, uint32_t a2, uint32_t a3,
    uint32_t b0, uint32_t b1)
{
    asm volatile(
        "mma.sync.aligned.m16n8k16.row.col.f32.f16.f16.f32 "
        "{%0,%1,%2,%3}, {%4,%5,%6,%7}, {%8,%9}, {%0,%1,%2,%3};"
        : "+f"(c0), "+f"(c1), "+f"(c2), "+f"(c3)
        : "r"(a0), "r"(a1), "r"(a2), "r"(a3), "r"(b0), "r"(b1));
}

// k index for interleaved u32 position (fragment = one LDS.64)
__device__ __forceinline__ int k_of(int pos, int e) {
    int ks = pos >> 3, q = pos & 7;
    return ks * 16 + (q & 1) * 8 + (q >> 1) * 2 + e;
}

// ---------------------------------------------------------------------------
// Kernel 1: fused adjacency scan + gather + per-feature top-8 + fp16 hi/lo.
// ---------------------------------------------------------------------------
__global__ void __launch_bounds__(256) scan_gather_kernel(
    const int* __restrict__ adj, const float* __restrict__ feat, int n)
{
    const int node = blockIdx.x;
    __shared__ int s_cnt;
    __shared__ int s_idx[DEG];
    if (threadIdx.x == 0) s_cnt = 0;
    __syncthreads();

    const int4* rp = reinterpret_cast<const int4*>(adj + (size_t)node * (size_t)n);
    int nvec = n >> 2;
    for (int i = threadIdx.x; i < nvec; i += blockDim.x) {
        int4 v = rp[i];
        if (v.x | v.y | v.z | v.w) {
            int base = 4 * i;
            if (v.x) { int p = atomicAdd(&s_cnt, 1); if (p < DEG) s_idx[p] = base;     }
            if (v.y) { int p = atomicAdd(&s_cnt, 1); if (p < DEG) s_idx[p] = base + 1; }
            if (v.z) { int p = atomicAdd(&s_cnt, 1); if (p < DEG) s_idx[p] = base + 2; }
            if (v.w) { int p = atomicAdd(&s_cnt, 1); if (p < DEG) s_idx[p] = base + 3; }
        }
    }
    for (int j = (nvec << 2) + threadIdx.x; j < n; j += blockDim.x) {
        if (adj[(size_t)node * (size_t)n + j]) {
            int p = atomicAdd(&s_cnt, 1); if (p < DEG) s_idx[p] = j;
        }
    }
    __syncthreads();
    const int cnt = min(s_cnt, DEG);

    if (threadIdx.x < DFEAT) {
        const int d = threadIdx.x;
        float t8[KTOP];
#pragma unroll
        for (int k = 0; k < KTOP; k++) t8[k] = -INFINITY;
        for (int j = 0; j < cnt; j++) {
            float v = __ldg(&feat[(size_t)s_idx[j] * DFEAT + d]);
            if (v > t8[KTOP - 1]) {
                t8[KTOP - 1] = v;
#pragma unroll
                for (int k = KTOP - 2; k >= 0; k--) {
                    if (t8[k + 1] > t8[k]) {
                        float tmp = t8[k]; t8[k] = t8[k + 1]; t8[k + 1] = tmp;
                    }
                }
            }
        }
#pragma unroll
        for (int k = 0; k < KTOP; k++)
            if (t8[k] == -INFINITY) t8[k] = 0.0f;
        if (cnt < KTOP) {
#pragma unroll
            for (int a = 1; a < KTOP; a++) {
#pragma unroll
                for (int bq = a; bq >= 1; bq--) {
                    if (t8[bq] > t8[bq - 1]) {
                        float tmp = t8[bq - 1]; t8[bq - 1] = t8[bq]; t8[bq] = tmp;
                    }
                }
            }
        }
        float rows[9];
        rows[0] = feat[(size_t)node * DFEAT + d];
#pragma unroll
        for (int k = 0; k < KTOP; k++) rows[1 + k] = t8[k];
        unsigned* sp = g_sel + (size_t)node * (9 * DFEAT) + d;
#pragma unroll
        for (int c = 0; c < 9; c++) {
            float v = rows[c];
            __half hb = __float2half(v);
            __half lb = __float2half(v - __half2float(hb));
            unsigned hi = (unsigned)__half_as_ushort(hb);
            unsigned lo = (unsigned)__half_as_ushort(lb);
            sp[c * DFEAT] = hi | (lo << 16);
        }
    }
}

// ---------------------------------------------------------------------------
// Kernel 2: persistent im2col + HMMA GEMM. 512 threads (16 warps), 148 CTAs.
// Warp w: mg=w>>1 owns A rows [mg*16, mg*16+16) (in registers, 48 regs);
// nh=w&1 owns n-tiles of x in [nh*64, ...). Double-buffered B + sel -> one
// barrier per node; MMA(i) | build(i+1) | stage sel(i+2) | LDG sel(i+3)
// all overlap across warps.
// ---------------------------------------------------------------------------
__global__ void __launch_bounds__(512, 1) gemm_kernel(
    const float* __restrict__ w,
    const float* __restrict__ bias,
    float* __restrict__ out, int n)
{
    extern __shared__ uint32_t dynsm[];          // 2 * BUFU32
    __shared__ uint32_t sel_sm[2 * 9 * SELW2];

    const int tid  = threadIdx.x;
    const int wid  = tid >> 5;
    const int lane = tid & 31;
    const int g    = lane >> 2;
    const int tc   = lane & 3;
    const int mg   = wid >> 1;
    const int nh   = wid & 1;
    const int nc   = nh ? 7 : 8;
    const int G    = gridDim.x;
    const int n0   = blockIdx.x;

    const float b0v = bias[mg * 16 + g];
    const float b1v = bias[mg * 16 + 8 + g];

    // ---- stage A = [whi | whi] fp16 into buf0 (interleaved layout) ----
    {
        const int o = tid >> 2, qi = tid & 3;
        uint32_t* arow = dynsm + (size_t)o * RST + qi * 24;
        const float* wrow = w + o * 81;
#pragma unroll
        for (int j4 = 0; j4 < 6; j4++) {
            uint32_t vv[4];
#pragma unroll
            for (int u = 0; u < 4; u++) {
                const int pos = qi * 24 + j4 * 4 + u;
                unsigned hv[2];
#pragma unroll
                for (int e = 0; e < 2; e++) {
                    const int k = k_of(pos, e);
                    unsigned bits = 0;
                    if (k < KVALID) {
                        const int kp = (k >= 81) ? (k - 81) : k;
                        bits = (unsigned)__half_as_ushort(__float2half(wrow[kp]));
                    }
                    hv[e] = bits;
                }
                vv[u] = hv[0] | (hv[1] << 16);
            }
            *reinterpret_cast<uint4*>(arow + j4 * 4) =
                make_uint4(vv[0], vv[1], vv[2], vv[3]);
        }
    }
    // prefetch sel(n0)
    uint32_t selr[3];
    if (n0 < n) {
#pragma unroll
        for (int q = 0; q < 3; q++) {
            int i = tid + q * 512;
            if (i < 1152) selr[q] = g_sel[(size_t)n0 * 1152 + i];
        }
    }
    __syncthreads();

    // ---- load A fragments into registers ----
    uint32_t a[KSTEPS][4];
    {
        const uint32_t* r0 = dynsm + (size_t)(mg * 16 + g) * RST + tc * 2;
        const uint32_t* r1 = r0 + 8 * RST;
#pragma unroll
        for (int ks = 0; ks < KSTEPS; ks++) {
            uint2 x = *reinterpret_cast<const uint2*>(r0 + ks * 8);
            uint2 y = *reinterpret_cast<const uint2*>(r1 + ks * 8);
            a[ks][0] = x.x; a[ks][1] = y.x;
            a[ks][2] = x.y; a[ks][3] = y.y;
        }
    }
    // stage sel(n0) -> selS0
    if (n0 < n) {
#pragma unroll
        for (int q = 0; q < 3; q++) {
            int i = tid + q * 512;
            if (i < 1152) sel_sm[(i >> 7) * SELW2 + (i & 127)] = selr[q];
        }
    }
    // prefetch sel(n0+G)
    if (n0 + G < n) {
#pragma unroll
        for (int q = 0; q < 3; q++) {
            int i = tid + q * 512;
            if (i < 1152) selr[q] = g_sel[(size_t)(n0 + G) * 1152 + i];
        }
    }
    __syncthreads();   // A frags read; selS0 staged

    // ---- build B(n0) into buf0 ----
    if (n0 < n && tid < 480) {
        const int d = tid >> 2, qi = tid & 3;
        uint32_t* brow = dynsm + (size_t)d * RST + qi * 24;
        const uint32_t* selp = sel_sm;
#pragma unroll
        for (int j4 = 0; j4 < 6; j4++) {
            uint32_t vv[4];
#pragma unroll
            for (int u = 0; u < 4; u++) {
                const int pos = qi * 24 + j4 * 4 + u;
                unsigned hv[2];
#pragma unroll
                for (int e = 0; e < 2; e++) {
                    const int k = k_of(pos, e);
                    unsigned bits = 0;
                    if (k < KVALID) {
                        const int p = (k >= 81) ? 1 : 0;
                        const int kp = k - 81 * p;
                        const int c = kp / 9, t = kp - 9 * c;
                        uint32_t pk = selp[c * SELW2 + d + t];
                        bits = p ? (pk >> 16) : (pk & 0xffffu);
                    }
                    hv[e] = bits;
                }
                vv[u] = hv[0] | (hv[1] << 16);
            }
            *reinterpret_cast<uint4*>(brow + j4 * 4) =
                make_uint4(vv[0], vv[1], vv[2], vv[3]);
        }
    }
    // stage sel(n0+G) -> selS1
    if (n0 + G < n) {
#pragma unroll
        for (int q = 0; q < 3; q++) {
            int i = tid + q * 512;
            if (i < 1152) sel_sm[9 * SELW2 + (i >> 7) * SELW2 + (i & 127)] = selr[q];
        }
    }
    // prefetch sel(n0+2G)
    if ((size_t)n0 + 2 * (size_t)G < (size_t)n) {
#pragma unroll
        for (int q = 0; q < 3; q++) {
            int i = tid + q * 512;
            if (i < 1152) selr[q] = g_sel[((size_t)n0 + 2 * (size_t)G) * 1152 + i];
        }
    }

    int cur = 0;
    for (int node = n0; node < n; node += G, cur ^= 1) {
        __syncthreads();   // the ONE barrier per node

        // ---- MMA(node) on buf[cur] ----
        float acc[8][4];
#pragma unroll
        for (int t = 0; t < 8; t++)
#pragma unroll
            for (int q = 0; q < 4; q++) acc[t][q] = 0.0f;

        const uint32_t* Bb = dynsm + (size_t)cur * BUFU32
                           + (size_t)(nh * 64 + g) * RST + tc * 2;
#pragma unroll
        for (int ks = 0; ks < KSTEPS; ks++) {
#pragma unroll
            for (int t = 0; t < 8; t++) {
                if (t < nc) {
                    uint2 b = *reinterpret_cast<const uint2*>(
                        Bb + (size_t)(t * 8) * RST + ks * 8);
                    mma_fp16(acc[t][0], acc[t][1], acc[t][2], acc[t][3],
                             a[ks][0], a[ks][1], a[ks][2], a[ks][3], b.x, b.y);
                }
            }
        }

        // ---- build B(node+G) into buf[cur^1] from selS[cur^1] ----
        if (node + G < n && tid < 480) {
            const int d = tid >> 2, qi = tid & 3;
            uint32_t* brow = dynsm + (size_t)(cur ^ 1) * BUFU32 + (size_t)d * RST + qi * 24;
            const uint32_t* selp = sel_sm + (cur ^ 1) * 9 * SELW2;
#pragma unroll
            for (int j4 = 0; j4 < 6; j4++) {
                uint32_t vv[4];
#pragma unroll
                for (int u = 0; u < 4; u++) {
                    const int pos = qi * 24 + j4 * 4 + u;
                    unsigned hv[2];
#pragma unroll
                    for (int e = 0; e < 2; e++) {
                        const int k = k_of(pos, e);
                        unsigned bits = 0;
                        if (k < KVALID) {
                            const int p = (k >= 81) ? 1 : 0;
                            const int kp = k - 81 * p;
                            const int c = kp / 9, t = kp - 9 * c;
                            uint32_t pk = selp[c * SELW2 + d + t];
                            bits = p ? (pk >> 16) : (pk & 0xffffu);
                        }
                        hv[e] = bits;
                    }
                    vv[u] = hv[0] | (hv[1] << 16);
                }
                *reinterpret_cast<uint4*>(brow + j4 * 4) =
                    make_uint4(vv[0], vv[1], vv[2], vv[3]);
            }
        }

        // ---- stage sel(node+2G) -> selS[cur] ----
        if ((size_t)node + 2 * (size_t)G < (size_t)n) {
#pragma unroll
            for (int q = 0; q < 3; q++) {
                int i = tid + q * 512;
                if (i < 1152) sel_sm[cur * 9 * SELW2 + (i >> 7) * SELW2 + (i & 127)] = selr[q];
            }
        }
        // ---- prefetch sel(node+3G) ----
        if ((size_t)node + 3 * (size_t)G < (size_t)n) {
#pragma unroll
            for (int q = 0; q < 3; q++) {
                int i = tid + q * 512;
                if (i < 1152) selr[q] = g_sel[((size_t)node + 3 * (size_t)G) * 1152 + i];
            }
        }

        // ---- epilogue(node): bias + float2 stores ----
        {
            float* obase = out + (size_t)node * (OUT_CH * XOUT);
            const int r0 = mg * 16 + g;
            float* p0 = obase + (size_t)r0 * XOUT + nh * 64 + tc * 2;
            float* p1 = p0 + (size_t)8 * XOUT;
#pragma unroll
            for (int t = 0; t < 8; t++) {
                if (t < nc) {
                    *reinterpret_cast<float2*>(p0 + t * 8) =
                        make_float2(acc[t][0] + b0v, acc[t][1] + b0v);
                    *reinterpret_cast<float2*>(p1 + t * 8) =
                        make_float2(acc[t][2] + b1v, acc[t][3] + b1v);
                }
            }
        }
    }
}

// ---------------------------------------------------------------------------
extern "C" void kernel_launch(void* const* d_in, const int* in_sizes, int n_in,
                              void* d_out, int out_size)
{
    const float* feat = (const float*)d_in[0];
    const int*   adj  = (const int*)d_in[1];
    const float* w    = (const float*)d_in[2];
    const float* b    = (const float*)d_in[3];
    float*       out  = (float*)d_out;

    int n = in_sizes[0] / DFEAT;
    if (n > MAXN) n = MAXN;

    const int dyn_bytes = 2 * BUFU32 * sizeof(uint32_t);   // 106,496 B
    cudaFuncSetAttribute(gemm_kernel, cudaFuncAttributeMaxDynamicSharedMemorySize,
                         dyn_bytes);

    scan_gather_kernel<<<n, 256>>>(adj, feat, n);
    gemm_kernel<<<148, 512, dyn_bytes>>>(w, b, out, n);
}

// round 8
// speedup vs baseline: 1.8749x; 1.8749x over previous
#include <cuda_runtime.h>
#include <cuda_fp16.h>
#include <cstdint>

// Problem constants
#define DFEAT   128
#define KTOP    8
#define DEG     32
#define OUT_CH  128
#define XOUT    120
#define MAXN    10000

// GEMM: K = 2 parts * 81 = 162 valid, padded to 192 = 12 k-steps of 16
#define KVALID  162
#define KSTEPS  12
#define RST     104        // u32 row stride (mod 32 = 8 -> conflict-free LDS.64)
#define SELW2   132        // u32 row stride of staged sel rows
#define NT      15         // n-tiles (120 / 8)

__device__ unsigned g_sel[MAXN * 9 * DFEAT];   // packed fp16: bhi | blo<<16

// ---------------------------------------------------------------------------
// fp16 mma.sync (m16n8k16, row.col, f32 accum)
// ---------------------------------------------------------------------------
__device__ __forceinline__ void mma_fp16(
    float& c0, float& c1, float& c2, float& c3,
    uint32_t a0, uint32_t a1, uint32_t a2, uint32_t a3,
    uint32_t b0, uint32_t b1)
{
    asm volatile(
        "mma.sync.aligned.m16n8k16.row.col.f32.f16.f16.f32 "
        "{%0,%1,%2,%3}, {%4,%5,%6,%7}, {%8,%9}, {%0,%1,%2,%3};"
        : "+f"(c0), "+f"(c1), "+f"(c2), "+f"(c3)
        : "r"(a0), "r"(a1), "r"(a2), "r"(a3), "r"(b0), "r"(b1));
}

// k index for interleaved u32 position (fragment pair = one LDS.64)
__device__ __forceinline__ int k_of(int pos, int e) {
    int ks = pos >> 3, q = pos & 7;
    return ks * 16 + (q & 1) * 8 + (q >> 1) * 2 + e;
}

// ---------------------------------------------------------------------------
// Kernel 1: fused adjacency scan + gather + per-feature top-8 + fp16 hi/lo.
// One block per node; HBM-bound on the 400MB adjacency.
// ---------------------------------------------------------------------------
__global__ void __launch_bounds__(256) scan_gather_kernel(
    const int* __restrict__ adj, const float* __restrict__ feat, int n)
{
    const int node = blockIdx.x;
    __shared__ int s_cnt;
    __shared__ int s_idx[DEG];
    if (threadIdx.x == 0) s_cnt = 0;
    __syncthreads();

    const int4* rp = reinterpret_cast<const int4*>(adj + (size_t)node * (size_t)n);
    int nvec = n >> 2;
    for (int i = threadIdx.x; i < nvec; i += blockDim.x) {
        int4 v = rp[i];
        if (v.x | v.y | v.z | v.w) {
            int base = 4 * i;
            if (v.x) { int p = atomicAdd(&s_cnt, 1); if (p < DEG) s_idx[p] = base;     }
            if (v.y) { int p = atomicAdd(&s_cnt, 1); if (p < DEG) s_idx[p] = base + 1; }
            if (v.z) { int p = atomicAdd(&s_cnt, 1); if (p < DEG) s_idx[p] = base + 2; }
            if (v.w) { int p = atomicAdd(&s_cnt, 1); if (p < DEG) s_idx[p] = base + 3; }
        }
    }
    for (int j = (nvec << 2) + threadIdx.x; j < n; j += blockDim.x) {
        if (adj[(size_t)node * (size_t)n + j]) {
            int p = atomicAdd(&s_cnt, 1); if (p < DEG) s_idx[p] = j;
        }
    }
    __syncthreads();
    const int cnt = min(s_cnt, DEG);

    if (threadIdx.x < DFEAT) {
        const int d = threadIdx.x;
        float t8[KTOP];
#pragma unroll
        for (int k = 0; k < KTOP; k++) t8[k] = -INFINITY;
        for (int j = 0; j < cnt; j++) {
            float v = __ldg(&feat[(size_t)s_idx[j] * DFEAT + d]);
            if (v > t8[KTOP - 1]) {
                t8[KTOP - 1] = v;
#pragma unroll
                for (int k = KTOP - 2; k >= 0; k--) {
                    if (t8[k + 1] > t8[k]) {
                        float tmp = t8[k]; t8[k] = t8[k + 1]; t8[k + 1] = tmp;
                    }
                }
            }
        }
#pragma unroll
        for (int k = 0; k < KTOP; k++)
            if (t8[k] == -INFINITY) t8[k] = 0.0f;
        if (cnt < KTOP) {
#pragma unroll
            for (int a = 1; a < KTOP; a++) {
#pragma unroll
                for (int bq = a; bq >= 1; bq--) {
                    if (t8[bq] > t8[bq - 1]) {
                        float tmp = t8[bq - 1]; t8[bq - 1] = t8[bq]; t8[bq] = tmp;
                    }
                }
            }
        }
        float rows[9];
        rows[0] = feat[(size_t)node * DFEAT + d];
#pragma unroll
        for (int k = 0; k < KTOP; k++) rows[1 + k] = t8[k];
        unsigned* sp = g_sel + (size_t)node * (9 * DFEAT) + d;
#pragma unroll
        for (int c = 0; c < 9; c++) {
            float v = rows[c];
            __half hb = __float2half(v);
            __half lb = __float2half(v - __half2float(hb));
            sp[c * DFEAT] = (unsigned)__half_as_ushort(hb)
                          | ((unsigned)__half_as_ushort(lb) << 16);
        }
    }
}

// ---------------------------------------------------------------------------
// Kernel 2: persistent im2col + HMMA GEMM. 256 threads (8 warps), 2 CTAs/SM.
// Warp w = m16 tile rows [w*16, w*16+16) (A in 48 regs) x full n120.
// Per node: stage sel -> build B -> MMA (prefetch next sel under it) -> store.
// Cross-CTA phase alternation (2 resident CTAs) hides the serialization.
// ---------------------------------------------------------------------------
__global__ void __launch_bounds__(256, 2) gemm_kernel(
    const float* __restrict__ w,
    const float* __restrict__ bias,
    float* __restrict__ out, int n)
{
    extern __shared__ uint32_t Bsm[];            // 128 * RST u32 (A staging, then B)
    __shared__ uint32_t sel_sm[9 * SELW2];

    const int tid  = threadIdx.x;
    const int wid  = tid >> 5;
    const int lane = tid & 31;
    const int g    = lane >> 2;
    const int tc   = lane & 3;
    const int G    = gridDim.x;

    const float b0v = bias[wid * 16 + g];
    const float b1v = bias[wid * 16 + 8 + g];

    // ---- stage A = whi (duplicated across both K parts) into Bsm ----
    {
        const int o = tid >> 1, h2 = tid & 1;
        uint32_t* arow = Bsm + (size_t)o * RST + h2 * 48;
        const float* wrow = w + o * 81;
#pragma unroll
        for (int j4 = 0; j4 < 12; j4++) {
            uint32_t vv[4];
#pragma unroll
            for (int u = 0; u < 4; u++) {
                const int pos = h2 * 48 + j4 * 4 + u;
                unsigned hv[2];
#pragma unroll
                for (int e = 0; e < 2; e++) {
                    const int k = k_of(pos, e);
                    unsigned bits = 0;
                    if (k < KVALID) {
                        const int kp = (k >= 81) ? (k - 81) : k;
                        bits = (unsigned)__half_as_ushort(__float2half(wrow[kp]));
                    }
                    hv[e] = bits;
                }
                vv[u] = hv[0] | (hv[1] << 16);
            }
            *reinterpret_cast<uint4*>(arow + j4 * 4) =
                make_uint4(vv[0], vv[1], vv[2], vv[3]);
        }
    }
    // prefetch sel(first node)
    uint32_t selr[5];
    int node = blockIdx.x;
    if (node < n) {
#pragma unroll
        for (int q = 0; q < 5; q++) {
            int i = tid + q * 256;
            if (i < 1152) selr[q] = g_sel[(size_t)node * 1152 + i];
        }
    }
    __syncthreads();

    // ---- load this warp's A fragments into registers ----
    uint32_t a[KSTEPS][4];
    {
        const uint32_t* r0 = Bsm + (size_t)(wid * 16 + g) * RST + tc * 2;
        const uint32_t* r1 = r0 + 8 * RST;
#pragma unroll
        for (int ks = 0; ks < KSTEPS; ks++) {
            uint2 x = *reinterpret_cast<const uint2*>(r0 + ks * 8);
            uint2 y = *reinterpret_cast<const uint2*>(r1 + ks * 8);
            a[ks][0] = x.x; a[ks][2] = x.y;
            a[ks][1] = y.x; a[ks][3] = y.y;
        }
    }
    __syncthreads();   // A consumed; Bsm becomes the B buffer

    for (; node < n; node += G) {
        // ---- stage sel(node) into smem ----
#pragma unroll
        for (int q = 0; q < 5; q++) {
            int i = tid + q * 256;
            if (i < 1152) sel_sm[(i >> 7) * SELW2 + (i & 127)] = selr[q];
        }
        __syncthreads();

        // ---- build B (120 rows, 2 threads per row, 48 u32 each) ----
        if (tid < 240) {
            const int d = tid >> 1, h2 = tid & 1;
            uint32_t* brow = Bsm + (size_t)d * RST + h2 * 48;
#pragma unroll
            for (int j4 = 0; j4 < 12; j4++) {
                uint32_t vv[4];
#pragma unroll
                for (int u = 0; u < 4; u++) {
                    const int pos = h2 * 48 + j4 * 4 + u;
                    unsigned hv[2];
#pragma unroll
                    for (int e = 0; e < 2; e++) {
                        const int k = k_of(pos, e);
                        unsigned bits = 0;
                        if (k < KVALID) {
                            const int p = (k >= 81) ? 1 : 0;
                            const int kp = k - 81 * p;
                            const int c = kp / 9, t = kp - 9 * c;
                            uint32_t pk = sel_sm[c * SELW2 + d + t];
                            bits = p ? (pk >> 16) : (pk & 0xffffu);
                        }
                        hv[e] = bits;
                    }
                    vv[u] = hv[0] | (hv[1] << 16);
                }
                *reinterpret_cast<uint4*>(brow + j4 * 4) =
                    make_uint4(vv[0], vv[1], vv[2], vv[3]);
            }
        }
        __syncthreads();

        // ---- prefetch next node's sel (hides under the MMA below) ----
        {
            int nxt = node + G;
            if (nxt < n) {
#pragma unroll
                for (int q = 0; q < 5; q++) {
                    int i = tid + q * 256;
                    if (i < 1152) selr[q] = g_sel[(size_t)nxt * 1152 + i];
                }
            }
        }

        // ---- MMA: warp = m16 x n120, K=192 ----
        float acc[NT][4];
#pragma unroll
        for (int t = 0; t < NT; t++)
#pragma unroll
            for (int q = 0; q < 4; q++) acc[t][q] = 0.0f;

        const uint32_t* Bb = Bsm + (size_t)g * RST + tc * 2;
#pragma unroll
        for (int ks = 0; ks < KSTEPS; ks++) {
#pragma unroll
            for (int t = 0; t < NT; t++) {
                uint2 b = *reinterpret_cast<const uint2*>(
                    Bb + (size_t)(t * 8) * RST + ks * 8);
                mma_fp16(acc[t][0], acc[t][1], acc[t][2], acc[t][3],
                         a[ks][0], a[ks][1], a[ks][2], a[ks][3], b.x, b.y);
            }
        }

        // ---- epilogue: bias + float2 stores ----
        {
            float* obase = out + (size_t)node * (OUT_CH * XOUT);
            const int r0 = wid * 16 + g;
            float* p0 = obase + (size_t)r0 * XOUT + tc * 2;
            float* p1 = p0 + (size_t)8 * XOUT;
#pragma unroll
            for (int t = 0; t < NT; t++) {
                *reinterpret_cast<float2*>(p0 + t * 8) =
                    make_float2(acc[t][0] + b0v, acc[t][1] + b0v);
                *reinterpret_cast<float2*>(p1 + t * 8) =
                    make_float2(acc[t][2] + b1v, acc[t][3] + b1v);
            }
        }
        __syncthreads();   // B + sel_sm consumed before next iteration
    }
}

// ---------------------------------------------------------------------------
extern "C" void kernel_launch(void* const* d_in, const int* in_sizes, int n_in,
                              void* d_out, int out_size)
{
    const float* feat = (const float*)d_in[0];
    const int*   adj  = (const int*)d_in[1];
    const float* w    = (const float*)d_in[2];
    const float* b    = (const float*)d_in[3];
    float*       out  = (float*)d_out;

    int n = in_sizes[0] / DFEAT;
    if (n > MAXN) n = MAXN;

    const int dyn_bytes = 128 * RST * sizeof(uint32_t);   // 53,248 B
    cudaFuncSetAttribute(gemm_kernel, cudaFuncAttributeMaxDynamicSharedMemorySize,
                         dyn_bytes);

    scan_gather_kernel<<<n, 256>>>(adj, feat, n);
    gemm_kernel<<<296, 256, dyn_bytes>>>(w, b, out, n);
}